// round 2
// baseline (speedup 1.0000x reference)
#include <cuda_runtime.h>

#define NC    6
#define NBINS 36
#define NWARPS 8
#define TPB   256

// Global confusion-matrix counters (scratch; __device__ global per harness rules).
__device__ unsigned int g_conf[NBINS];

__global__ void zero_conf_kernel() {
    if (threadIdx.x < NBINS) g_conf[threadIdx.x] = 0u;
}

// Main streaming kernel: 4 rows per thread iteration, vectorized loads,
// per-warp shared histograms, deterministic integer atomics.
__global__ void __launch_bounds__(TPB) kappa_hist_kernel(
    const float* __restrict__ yp,
    const int* __restrict__ yt,     // y_true is int32 (JAX x64-demotion)
    int n)
{
    __shared__ unsigned int sh[NWARPS][NBINS];
    const int tid  = threadIdx.x;
    const int warp = tid >> 5;

    for (int i = tid; i < NWARPS * NBINS; i += TPB)
        ((unsigned int*)sh)[i] = 0u;
    __syncthreads();

    const int ngroups = n >> 2;                   // groups of 4 rows
    const float4* yp4 = (const float4*)yp;        // 6 float4 per group (24 floats)
    const int4*   yt4 = (const int4*)yt;          // 1 int4 per group (4 labels)
    const int stride = gridDim.x * blockDim.x;

    for (int g = blockIdx.x * blockDim.x + tid; g < ngroups; g += stride) {
        float4 f0 = yp4[(size_t)g * 6 + 0];
        float4 f1 = yp4[(size_t)g * 6 + 1];
        float4 f2 = yp4[(size_t)g * 6 + 2];
        float4 f3 = yp4[(size_t)g * 6 + 3];
        float4 f4 = yp4[(size_t)g * 6 + 4];
        float4 f5 = yp4[(size_t)g * 6 + 5];
        int4   t4 = yt4[g];

        float v[24];
        v[0]=f0.x;  v[1]=f0.y;  v[2]=f0.z;  v[3]=f0.w;
        v[4]=f1.x;  v[5]=f1.y;  v[6]=f1.z;  v[7]=f1.w;
        v[8]=f2.x;  v[9]=f2.y;  v[10]=f2.z; v[11]=f2.w;
        v[12]=f3.x; v[13]=f3.y; v[14]=f3.z; v[15]=f3.w;
        v[16]=f4.x; v[17]=f4.y; v[18]=f4.z; v[19]=f4.w;
        v[20]=f5.x; v[21]=f5.y; v[22]=f5.z; v[23]=f5.w;

        int tt[4];
        tt[0] = t4.x; tt[1] = t4.y; tt[2] = t4.z; tt[3] = t4.w;

        #pragma unroll
        for (int r = 0; r < 4; r++) {
            const int base = r * 6;
            float bv = v[base];
            int   bi = 0;
            #pragma unroll
            for (int c = 1; c < 6; c++) {
                // strict > keeps FIRST max, matching jnp.argmax tie-break
                if (v[base + c] > bv) { bv = v[base + c]; bi = c; }
            }
            atomicAdd(&sh[warp][tt[r] * NC + bi], 1u);
        }
    }

    // Tail rows (n % 4), handled scalar by block 0.
    if (blockIdx.x == 0 && tid < (n & 3)) {
        const int r = (n & ~3) + tid;
        const float* row = yp + (size_t)r * 6;
        float bv = row[0];
        int   bi = 0;
        #pragma unroll
        for (int c = 1; c < 6; c++) {
            float x = row[c];
            if (x > bv) { bv = x; bi = c; }
        }
        atomicAdd(&sh[warp][yt[r] * NC + bi], 1u);
    }

    __syncthreads();
    if (tid < NBINS) {
        unsigned int s = 0;
        #pragma unroll
        for (int w = 0; w < NWARPS; w++) s += sh[w][tid];
        if (s) atomicAdd(&g_conf[tid], s);
    }
}

// Finalize: closed-form quadratic-weighted kappa from the 36 counts.
// kappa = 1 - (sum W*conf) * N / (sum W*ht[i]*hp[j])
__global__ void kappa_finalize_kernel(float* __restrict__ out) {
    if (threadIdx.x == 0 && blockIdx.x == 0) {
        double conf[NBINS];
        double ht[NC] = {0}, hp[NC] = {0};
        double tot = 0.0;
        #pragma unroll
        for (int i = 0; i < NBINS; i++) {
            conf[i] = (double)g_conf[i];
            tot += conf[i];
        }
        #pragma unroll
        for (int i = 0; i < NC; i++)
            #pragma unroll
            for (int j = 0; j < NC; j++) {
                ht[i] += conf[i * NC + j];
                hp[j] += conf[i * NC + j];
            }
        double num = 0.0, den = 0.0;
        #pragma unroll
        for (int i = 0; i < NC; i++)
            #pragma unroll
            for (int j = 0; j < NC; j++) {
                const double w = (double)((i - j) * (i - j));
                num += w * conf[i * NC + j];
                den += w * ht[i] * hp[j];
            }
        const double kappa = 1.0 - (num * tot) / den;
        out[0] = (float)kappa;
    }
}

extern "C" void kernel_launch(void* const* d_in, const int* in_sizes, int n_in,
                              void* d_out, int out_size) {
    const float* yp  = (const float*)d_in[0];
    const int*   yt  = (const int*)d_in[1];
    float*       out = (float*)d_out;
    const int n = in_sizes[1];   // number of rows (y_true element count)

    zero_conf_kernel<<<1, 64>>>();

    const int blocks = 1184;     // 148 SMs * 8, grid-stride covers all groups
    kappa_hist_kernel<<<blocks, TPB>>>(yp, yt, n);

    kappa_finalize_kernel<<<1, 32>>>(out);
}